// round 10
// baseline (speedup 1.0000x reference)
#include <cuda_runtime.h>
#include <math.h>

#define NPTS  2048
#define PAIRS 64
#define IVALS 16

// ---- scratch (no allocations allowed) --------------------------------------
__device__ float4   g_y[PAIRS * NPTS];      // transformed source: xyz + |y|^2
__device__ float4   g_x[IVALS * NPTS];      // target prescaled: -2x,-2y,-2z, |x|^2
__device__ unsigned g_colmin[PAIRS * NPTS]; // per-(pair,m) min d2, uint bits
__device__ float    g_rowpart[PAIRS * 16];  // per-(pair,nsplit) row-min sums

// ---------------------------------------------------------------------------
// Kernel 1: transform source, prescale target, init colmin (measured-best).
// ---------------------------------------------------------------------------
__global__ void __launch_bounds__(256) prep_kernel(const float* __restrict__ src,
                            const float* __restrict__ tgt,
                            const float* __restrict__ rot,
                            const float* __restrict__ trn,
                            const float* __restrict__ scl)
{
    __shared__ float M[13];
    const int pair  = blockIdx.x >> 3;
    const int pbase = (blockIdx.x & 7) * 256;

    if (threadIdx.x == 0) {
        float ax = rot[pair * 3 + 0], ay = rot[pair * 3 + 1], az = rot[pair * 3 + 2];
        float sx, cx, sy, cy, sz, cz;
        sincosf(ax, &sx, &cx);
        sincosf(ay, &sy, &cy);
        sincosf(az, &sz, &cz);
        M[0] = cy * cz;                M[1] = -cy * sz;               M[2] = sy;
        M[3] = cx * sz + sx * sy * cz; M[4] = cx * cz - sx * sy * sz; M[5] = -sx * cy;
        M[6] = sx * sz - cx * sy * cz; M[7] = sx * cz + cx * sy * sz; M[8] = cx * cy;
        M[9]  = trn[pair * 3 + 0];
        M[10] = trn[pair * 3 + 1];
        M[11] = trn[pair * 3 + 2];
        M[12] = scl[pair];
    }
    __syncthreads();

    const int idx = pair * NPTS + pbase + threadIdx.x;
    const float px = src[idx * 3 + 0];
    const float py = src[idx * 3 + 1];
    const float pz = src[idx * 3 + 2];
    const float s = M[12];
    const float qx = s * fmaf(M[0], px, fmaf(M[1], py, fmaf(M[2], pz, M[9])));
    const float qy = s * fmaf(M[3], px, fmaf(M[4], py, fmaf(M[5], pz, M[10])));
    const float qz = s * fmaf(M[6], px, fmaf(M[7], py, fmaf(M[8], pz, M[11])));

    g_y[idx] = make_float4(qx, qy, qz, qx * qx + qy * qy + qz * qz);
    g_colmin[idx] = 0x7F800000u;   // +inf bits

    if (pair < IVALS) {
        const float bx = tgt[idx * 3 + 0];
        const float by = tgt[idx * 3 + 1];
        const float bz = tgt[idx * 3 + 2];
        g_x[idx] = make_float4(-2.0f * bx, -2.0f * by, -2.0f * bz,
                               bx * bx + by * by + bz * bz);
    }
}

// ---------------------------------------------------------------------------
// Kernel 2: bidirectional chamfer, pipelined, 4 CTAs/SM target (regs <= 64).
// Block (nsplit, pair): 128 target rows x 2048 source cols, 16 chunks of 128.
// One barrier per chunk; next chunk staged straight to the other s_y buffer
// (LDG->STS stall absorbed where the barrier wait was); col-min reduce +
// atomicMin after the barrier overlaps the next chunk's compute.
// Thread (tn=t>>4 rows, tm=t&15 cols): 8x8 register tile.
//   c  = fma(xx,yx, fma(xy,yy, fma(xz,yz, yw)))   // |y|^2 - 2 x.y
//   rowmin over c (x2 deferred), colmin over c + x2.
// ---------------------------------------------------------------------------
__global__ void __launch_bounds__(256, 4) chamfer_kernel()
{
    const int pair   = blockIdx.y;
    const int nsplit = blockIdx.x;
    const int t  = threadIdx.x;
    const int tn = t >> 4;
    const int tm = t & 15;

    __shared__ float4 s_y[2][128];
    __shared__ float  s_red[2][16][129];
    __shared__ float  s_sum[8];

    const float4* gx = g_x + (pair & 15) * NPTS + nsplit * 128;
    const float4* gy = g_y + pair * NPTS;
    unsigned* cmin = g_colmin + pair * NPTS;

    float4 xf[8];
#pragma unroll
    for (int i = 0; i < 8; i++) xf[i] = gx[tn * 8 + i];

    float rm[8];
#pragma unroll
    for (int i = 0; i < 8; i++) rm[i] = 3.4e38f;

    // prologue: stage chunk 0
    if (t < 128) s_y[0][t] = gy[t];
    __syncthreads();

    for (int c = 0; c < 16; c++) {
        // stage next chunk directly to the other buffer (no long-lived regs);
        // the LDG->STS stall is absorbed by the other warps' compute.
        if (c < 15 && t < 128) s_y[(c + 1) & 1][t] = gy[(c + 1) * 128 + t];

        const float4* yb = &s_y[c & 1][0];

        float cm[8];
#pragma unroll
        for (int j = 0; j < 8; j++) cm[j] = 3.4e38f;

#pragma unroll
        for (int jj = 0; jj < 8; jj++) {
            const float4 y = yb[tm + 16 * jj];
#pragma unroll
            for (int i = 0; i < 8; i++) {
                float cc = fmaf(xf[i].x, y.x,
                           fmaf(xf[i].y, y.y,
                           fmaf(xf[i].z, y.z, y.w)));
                rm[i]  = fminf(rm[i], cc);
                cm[jj] = fminf(cm[jj], cc + xf[i].w);
            }
        }

        // stage col-min partials, then the chunk's ONE barrier
#pragma unroll
        for (int jj = 0; jj < 8; jj++) s_red[c & 1][tn][tm + 16 * jj] = cm[jj];
        __syncthreads();

        // reduce + atomic AFTER the barrier: overlaps next chunk's compute.
        if (t < 128) {
            float v = s_red[c & 1][0][t];
#pragma unroll
            for (int k = 1; k < 16; k++) v = fminf(v, s_red[c & 1][k][t]);
            v = fmaxf(v, 0.0f);          // d2 >= 0: keep uint ordering monotone
            atomicMin(&cmin[c * 128 + t], __float_as_uint(v));
        }
    }

    // finalize row mins: add deferred x2, reduce over tm, sum the 128 rows
#pragma unroll
    for (int i = 0; i < 8; i++) s_red[0][tm][tn * 8 + i] = rm[i] + xf[i].w;
    __syncthreads();

    float total = 0.0f;
    if (t < 128) {
        float v = s_red[0][0][t];
#pragma unroll
        for (int k = 1; k < 16; k++) v = fminf(v, s_red[0][k][t]);
        total = v;
    }
#pragma unroll
    for (int off = 16; off > 0; off >>= 1)
        total += __shfl_down_sync(0xffffffffu, total, off);
    if ((t & 31) == 0) s_sum[t >> 5] = total;
    __syncthreads();
    if (t == 0) {
        g_rowpart[pair * 16 + nsplit] =
            s_sum[0] + s_sum[1] + s_sum[2] + s_sum[3] +
            s_sum[4] + s_sum[5] + s_sum[6] + s_sum[7];
    }
}

// ---------------------------------------------------------------------------
// Kernel 3: per-pair means and combine
// ---------------------------------------------------------------------------
__global__ void final_kernel(float* __restrict__ out)
{
    const int pair = blockIdx.x;
    const int t = threadIdx.x;
    float local = 0.0f;
#pragma unroll
    for (int k = 0; k < 8; k++)
        local += __uint_as_float(g_colmin[pair * NPTS + t + 256 * k]);
    if (t < 16) local += g_rowpart[pair * 16 + t];

    __shared__ float sbuf[256];
    sbuf[t] = local;
    __syncthreads();
#pragma unroll
    for (int s = 128; s > 0; s >>= 1) {
        if (t < s) sbuf[t] += sbuf[t + s];
        __syncthreads();
    }
    if (t == 0) out[pair] = sbuf[0] * (1.0f / 2048.0f);
}

// ---------------------------------------------------------------------------
extern "C" void kernel_launch(void* const* d_in, const int* in_sizes, int n_in,
                              void* d_out, int out_size)
{
    const float* src = (const float*)d_in[0];   // [4,16,2048,3]
    const float* tgt = (const float*)d_in[1];   // [16,2048,3]
    const float* rot = (const float*)d_in[2];   // [4,16,3]
    const float* trn = (const float*)d_in[3];   // [4,16,3]
    const float* scl = (const float*)d_in[4];   // [4,16]
    (void)in_sizes; (void)n_in; (void)out_size;

    prep_kernel<<<512, 256>>>(src, tgt, rot, trn, scl);
    chamfer_kernel<<<dim3(16, PAIRS), 256>>>();
    final_kernel<<<PAIRS, 256>>>((float*)d_out);
}

// round 11
// speedup vs baseline: 1.0422x; 1.0422x over previous
#include <cuda_runtime.h>
#include <math.h>

#define NPTS  2048
#define PAIRS 64
#define IVALS 16

// ---- scratch (no allocations allowed) --------------------------------------
__device__ float4   g_y[PAIRS * NPTS];      // transformed source: xyz + |y|^2
__device__ float4   g_x[IVALS * NPTS];      // target prescaled: -2x,-2y,-2z, |x|^2
__device__ unsigned g_colmin[PAIRS * NPTS]; // per-(pair,m) min d2, uint bits
__device__ unsigned g_rowmin[PAIRS * NPTS]; // per-(pair,n) min d2, uint bits

// ---------------------------------------------------------------------------
// Kernel 1: transform source, prescale target, init colmin/rowmin.
// ---------------------------------------------------------------------------
__global__ void __launch_bounds__(256) prep_kernel(const float* __restrict__ src,
                            const float* __restrict__ tgt,
                            const float* __restrict__ rot,
                            const float* __restrict__ trn,
                            const float* __restrict__ scl)
{
    __shared__ float M[13];
    const int pair  = blockIdx.x >> 3;
    const int pbase = (blockIdx.x & 7) * 256;

    if (threadIdx.x == 0) {
        float ax = rot[pair * 3 + 0], ay = rot[pair * 3 + 1], az = rot[pair * 3 + 2];
        float sx, cx, sy, cy, sz, cz;
        sincosf(ax, &sx, &cx);
        sincosf(ay, &sy, &cy);
        sincosf(az, &sz, &cz);
        M[0] = cy * cz;                M[1] = -cy * sz;               M[2] = sy;
        M[3] = cx * sz + sx * sy * cz; M[4] = cx * cz - sx * sy * sz; M[5] = -sx * cy;
        M[6] = sx * sz - cx * sy * cz; M[7] = sx * cz + cx * sy * sz; M[8] = cx * cy;
        M[9]  = trn[pair * 3 + 0];
        M[10] = trn[pair * 3 + 1];
        M[11] = trn[pair * 3 + 2];
        M[12] = scl[pair];
    }
    __syncthreads();

    const int idx = pair * NPTS + pbase + threadIdx.x;
    const float px = src[idx * 3 + 0];
    const float py = src[idx * 3 + 1];
    const float pz = src[idx * 3 + 2];
    const float s = M[12];
    const float qx = s * fmaf(M[0], px, fmaf(M[1], py, fmaf(M[2], pz, M[9])));
    const float qy = s * fmaf(M[3], px, fmaf(M[4], py, fmaf(M[5], pz, M[10])));
    const float qz = s * fmaf(M[6], px, fmaf(M[7], py, fmaf(M[8], pz, M[11])));

    g_y[idx] = make_float4(qx, qy, qz, qx * qx + qy * qy + qz * qz);
    g_colmin[idx] = 0x7F800000u;   // +inf bits
    g_rowmin[idx] = 0x7F800000u;

    if (pair < IVALS) {
        const float bx = tgt[idx * 3 + 0];
        const float by = tgt[idx * 3 + 1];
        const float bz = tgt[idx * 3 + 2];
        g_x[idx] = make_float4(-2.0f * bx, -2.0f * by, -2.0f * bz,
                               bx * bx + by * by + bz * bz);
    }
}

// ---------------------------------------------------------------------------
// Kernel 2: bidirectional chamfer, pipelined (R9 loop), HALF-DURATION blocks
// to kill wave quantization: grid = (32, 64) -> 2048 blocks @ 3 CTAs/SM
// (444 slots): 5 half-waves vs ideal 4.61 -> 92% vs the old 77%.
// Block (x = nsplit*2 + half, pair): 128 target rows x 1024 source cols
// (8 chunks of 128). Both min directions flushed via global atomicMin.
// Thread (tn=t>>4 rows, tm=t&15 cols): 8x8 register tile.
//   c  = fma(xx,yx, fma(xy,yy, fma(xz,yz, yw)))   // |y|^2 - 2 x.y
//   rowmin over c (x2 deferred to flush), colmin over c + x2.
// ---------------------------------------------------------------------------
__global__ void __launch_bounds__(256, 3) chamfer_kernel()
{
    const int pair   = blockIdx.y;
    const int nsplit = blockIdx.x >> 1;
    const int half   = blockIdx.x & 1;
    const int t  = threadIdx.x;
    const int tn = t >> 4;
    const int tm = t & 15;

    __shared__ float4 s_y[2][128];
    __shared__ float  s_red[2][16][129];

    const float4* gx = g_x + (pair & 15) * NPTS + nsplit * 128;
    const float4* gy = g_y + pair * NPTS + half * 1024;
    unsigned* cmin = g_colmin + pair * NPTS + half * 1024;
    unsigned* rmin = g_rowmin + pair * NPTS + nsplit * 128;

    float4 xf[8];
#pragma unroll
    for (int i = 0; i < 8; i++) xf[i] = gx[tn * 8 + i];

    float rm[8];
#pragma unroll
    for (int i = 0; i < 8; i++) rm[i] = 3.4e38f;

    // prologue: stage chunk 0
    if (t < 128) s_y[0][t] = gy[t];
    __syncthreads();

    for (int c = 0; c < 8; c++) {
        // stage next chunk to the other buffer (hidden behind compute)
        if (c < 7 && t < 128) s_y[(c + 1) & 1][t] = gy[(c + 1) * 128 + t];

        const float4* yb = &s_y[c & 1][0];

        float cm[8];
#pragma unroll
        for (int j = 0; j < 8; j++) cm[j] = 3.4e38f;

#pragma unroll
        for (int jj = 0; jj < 8; jj++) {
            const float4 y = yb[tm + 16 * jj];
#pragma unroll
            for (int i = 0; i < 8; i++) {
                float cc = fmaf(xf[i].x, y.x,
                           fmaf(xf[i].y, y.y,
                           fmaf(xf[i].z, y.z, y.w)));
                rm[i]  = fminf(rm[i], cc);
                cm[jj] = fminf(cm[jj], cc + xf[i].w);
            }
        }

        // stage col-min partials, then the chunk's ONE barrier
#pragma unroll
        for (int jj = 0; jj < 8; jj++) s_red[c & 1][tn][tm + 16 * jj] = cm[jj];
        __syncthreads();

        // reduce + atomic AFTER the barrier: overlaps next chunk's compute
        if (t < 128) {
            float v = s_red[c & 1][0][t];
#pragma unroll
            for (int k = 1; k < 16; k++) v = fminf(v, s_red[c & 1][k][t]);
            v = fmaxf(v, 0.0f);          // d2 >= 0: keep uint ordering monotone
            atomicMin(&cmin[c * 128 + t], __float_as_uint(v));
        }
    }

    // row-min flush: add deferred x2, reduce over tm, then global atomicMin.
    // s_red[0]'s last readers finished before the final chunk's barrier.
#pragma unroll
    for (int i = 0; i < 8; i++) s_red[0][tm][tn * 8 + i] = rm[i] + xf[i].w;
    __syncthreads();

    if (t < 128) {
        float v = s_red[0][0][t];
#pragma unroll
        for (int k = 1; k < 16; k++) v = fminf(v, s_red[0][k][t]);
        v = fmaxf(v, 0.0f);
        atomicMin(&rmin[t], __float_as_uint(v));
    }
}

// ---------------------------------------------------------------------------
// Kernel 3: per-pair means of both min arrays, combine
// ---------------------------------------------------------------------------
__global__ void final_kernel(float* __restrict__ out)
{
    const int pair = blockIdx.x;
    const int t = threadIdx.x;
    float local = 0.0f;
#pragma unroll
    for (int k = 0; k < 8; k++) {
        local += __uint_as_float(g_colmin[pair * NPTS + t + 256 * k]);
        local += __uint_as_float(g_rowmin[pair * NPTS + t + 256 * k]);
    }

    __shared__ float sbuf[256];
    sbuf[t] = local;
    __syncthreads();
#pragma unroll
    for (int s = 128; s > 0; s >>= 1) {
        if (t < s) sbuf[t] += sbuf[t + s];
        __syncthreads();
    }
    if (t == 0) out[pair] = sbuf[0] * (1.0f / 2048.0f);
}

// ---------------------------------------------------------------------------
extern "C" void kernel_launch(void* const* d_in, const int* in_sizes, int n_in,
                              void* d_out, int out_size)
{
    const float* src = (const float*)d_in[0];   // [4,16,2048,3]
    const float* tgt = (const float*)d_in[1];   // [16,2048,3]
    const float* rot = (const float*)d_in[2];   // [4,16,3]
    const float* trn = (const float*)d_in[3];   // [4,16,3]
    const float* scl = (const float*)d_in[4];   // [4,16]
    (void)in_sizes; (void)n_in; (void)out_size;

    prep_kernel<<<512, 256>>>(src, tgt, rot, trn, scl);
    chamfer_kernel<<<dim3(32, PAIRS), 256>>>();
    final_kernel<<<PAIRS, 256>>>((float*)d_out);
}